// round 4
// baseline (speedup 1.0000x reference)
#include <cuda_runtime.h>

#define BB 1024
#define TT 200

// Precomputed x-dependent halves:
// g_Xg[m][j] = b_gate[j] + sum_k X[m][k]*W_gate[k][j]   (j in [0,256))
// g_Xc[m][j] = b_cand[j] + sum_k X[m][k]*W_cand[k][j]   (j in [0,128))
__device__ float g_Xg[(size_t)BB * TT * 256];
__device__ float g_Xc[(size_t)BB * TT * 128];

typedef unsigned long long u64;

__device__ __forceinline__ u64 pack2(float a, float b) {
    u64 r; asm("mov.b64 %0,{%1,%2};" : "=l"(r) : "f"(a), "f"(b)); return r;
}
__device__ __forceinline__ u64 splat2(float a) { return pack2(a, a); }
__device__ __forceinline__ void fma2(u64& d, u64 a, u64 b) {
    asm("fma.rn.f32x2 %0,%1,%2,%0;" : "+l"(d) : "l"(a), "l"(b));
}
__device__ __forceinline__ float2 unpack2(u64 v) {
    float2 r; asm("mov.b64 {%0,%1},%2;" : "=f"(r.x), "=f"(r.y) : "l"(v)); return r;
}

__device__ __forceinline__ float sigmoid_f(float x) {
    return __fdividef(1.0f, 1.0f + __expf(-x));
}
__device__ __forceinline__ float tanh_f(float x) {
    return 1.0f - __fdividef(2.0f, __expf(2.0f * x) + 1.0f);
}

// ---------------------------------------------------------------------------
// Kernel A: Xg/Xc precompute GEMM with packed f32x2 FMA.
// Block tile 64(M) x 128(N), K=128; loops nt=0..2 (gate lo / gate hi / cand)
// reusing the X tile in smem. 256 threads, each: 8 rows x 4 cols.
// ---------------------------------------------------------------------------
__global__ __launch_bounds__(256, 1)
void precompute_kernel(const float* __restrict__ X,
                       const float* __restrict__ Wg,
                       const float* __restrict__ bg,
                       const float* __restrict__ Wc,
                       const float* __restrict__ bc)
{
    extern __shared__ float sm[];
    float* Xs = sm;              // [64][132] row-major, padded
    float* Ws = sm + 64 * 132;   // [128][128]

    const int tid = threadIdx.x;
    const int m0  = blockIdx.x * 64;

    // Load X tile (64x128) coalesced.
    #pragma unroll
    for (int i = 0; i < 8; i++) {
        int idx = tid + i * 256;         // 2048 float4
        int m   = idx >> 5;
        int k4  = idx & 31;
        float4 v = *(const float4*)&X[(size_t)(m0 + m) * 128 + k4 * 4];
        *(float4*)&Xs[m * 132 + k4 * 4] = v;
    }

    const int colg = tid & 31;
    const int rowg = tid >> 5;
    const int c0 = colg * 4;             // 4 output cols
    const int r0 = rowg * 8;             // 8 rows

    for (int nt = 0; nt < 3; nt++) {
        __syncthreads();
        const float* Wsrc; int ldw, n0;
        if (nt < 2) { Wsrc = Wg; ldw = 256; n0 = nt * 128; }
        else        { Wsrc = Wc; ldw = 128; n0 = 0; }
        #pragma unroll
        for (int i = 0; i < 16; i++) {
            int idx = tid + i * 256;     // 4096 float4
            int k   = idx >> 5;
            int j4  = idx & 31;
            *(float4*)&Ws[k * 128 + j4 * 4] =
                *(const float4*)&Wsrc[(size_t)k * ldw + n0 + j4 * 4];
        }
        __syncthreads();

        u64 acc[8][2];
        #pragma unroll
        for (int r = 0; r < 8; r++) { acc[r][0] = 0ULL; acc[r][1] = 0ULL; }

        for (int k4 = 0; k4 < 32; k4++) {
            float4 xv[8];
            #pragma unroll
            for (int r = 0; r < 8; r++)
                xv[r] = *(const float4*)&Xs[(r0 + r) * 132 + k4 * 4];
            #pragma unroll
            for (int kk = 0; kk < 4; kk++) {
                ulonglong2 wv = *(const ulonglong2*)&Ws[(k4 * 4 + kk) * 128 + c0];
                #pragma unroll
                for (int r = 0; r < 8; r++) {
                    float xs = (kk == 0) ? xv[r].x : (kk == 1) ? xv[r].y
                             : (kk == 2) ? xv[r].z : xv[r].w;
                    u64 xp = splat2(xs);
                    fma2(acc[r][0], xp, wv.x);
                    fma2(acc[r][1], xp, wv.y);
                }
            }
        }

        if (nt < 2) {
            float4 bv = *(const float4*)&bg[n0 + c0];
            #pragma unroll
            for (int r = 0; r < 8; r++) {
                float2 a0 = unpack2(acc[r][0]), a1 = unpack2(acc[r][1]);
                float4 o = make_float4(a0.x + bv.x, a0.y + bv.y,
                                       a1.x + bv.z, a1.y + bv.w);
                *(float4*)&g_Xg[(size_t)(m0 + r0 + r) * 256 + n0 + c0] = o;
            }
        } else {
            float4 bv = *(const float4*)&bc[c0];
            #pragma unroll
            for (int r = 0; r < 8; r++) {
                float2 a0 = unpack2(acc[r][0]), a1 = unpack2(acc[r][1]);
                float4 o = make_float4(a0.x + bv.x, a0.y + bv.y,
                                       a1.x + bv.z, a1.y + bv.w);
                *(float4*)&g_Xc[(size_t)(m0 + r0 + r) * 128 + c0] = o;
            }
        }
    }
}

// ---------------------------------------------------------------------------
// Kernel B: GRU recurrence. 128 blocks x 128 threads; block owns 8 batch rows.
// State arrays are TRANSPOSED [col][row] with row-stride 12 (16B-aligned,
// broadcast-friendly matmul reads). Every thread handles all 8 rows:
//   Phase G: 2 gate cols (cg = 2*tid), rows packed in f32x2 pairs.
//   Phase C: 1 cand col (tid).
// Recurrent weights read ONCE per block per step.
// ---------------------------------------------------------------------------
#define SPAD 12

__global__ __launch_bounds__(128, 1)
void gru_kernel(const float* __restrict__ Wg,   // [256][256]
                const float* __restrict__ Wc,   // [256][128]
                const int*   __restrict__ seq_len,
                float* __restrict__ out)        // [1024][200][128]
{
    extern __shared__ float sm[];
    float* Wg_s = sm;                      // [128][256] h-part of W_gate
    float* Wc_s = Wg_s + 128 * 256;        // [128][128] h-part of W_cand
    float* h_s  = Wc_s + 128 * 128;        // [128][SPAD] transposed state
    float* rh_s = h_s  + 128 * SPAD;
    float* u_s  = rh_s + 128 * SPAD;

    const int tid = threadIdx.x;
    const int b0  = blockIdx.x * 8;

    // Load recurrent weights once.
    #pragma unroll
    for (int i = 0; i < 64; i++) {
        int idx = tid + i * 128;
        *(float4*)&Wg_s[idx * 4] = *(const float4*)&Wg[128 * 256 + idx * 4];
    }
    #pragma unroll
    for (int i = 0; i < 32; i++) {
        int idx = tid + i * 128;
        *(float4*)&Wc_s[idx * 4] = *(const float4*)&Wc[128 * 128 + idx * 4];
    }
    for (int i = tid; i < 128 * SPAD; i += 128) h_s[i] = 0.0f;
    __syncthreads();

    int sl[8];
    #pragma unroll
    for (int i = 0; i < 8; i++) sl[i] = seq_len[b0 + i];

    const int cg = tid * 2;                // gate cols cg, cg+1

    // Prefetch t=0 x-contributions.
    float2 xg[8]; float xc[8];
    #pragma unroll
    for (int i = 0; i < 8; i++) {
        xg[i] = *(const float2*)&g_Xg[((size_t)(b0 + i) * TT + 0) * 256 + cg];
        xc[i] = g_Xc[((size_t)(b0 + i) * TT + 0) * 128 + tid];
    }

    for (int t = 0; t < TT; t++) {
        // ---- Phase G: gates = sigmoid(xg + h @ Wg_h) -----------------------
        // acc[p][c] packs (row 2p, row 2p+1) for col cg+c.
        u64 acc[4][2];
        #pragma unroll
        for (int p = 0; p < 4; p++) {
            acc[p][0] = pack2(xg[2 * p].x, xg[2 * p + 1].x);
            acc[p][1] = pack2(xg[2 * p].y, xg[2 * p + 1].y);
        }

        // Prefetch next step's x-contributions (latency hidden by matmul).
        const int tn = (t + 1 < TT) ? t + 1 : t;
        float2 xg_n[8]; float xc_n[8];
        #pragma unroll
        for (int i = 0; i < 8; i++) {
            xg_n[i] = *(const float2*)&g_Xg[((size_t)(b0 + i) * TT + tn) * 256 + cg];
            xc_n[i] = g_Xc[((size_t)(b0 + i) * TT + tn) * 128 + tid];
        }

        #pragma unroll 4
        for (int k = 0; k < 128; k++) {
            float2 w = *(const float2*)&Wg_s[k * 256 + cg];
            u64 w0 = splat2(w.x), w1 = splat2(w.y);
            ulonglong2 hA = *(const ulonglong2*)&h_s[k * SPAD];     // rows 0-3
            ulonglong2 hB = *(const ulonglong2*)&h_s[k * SPAD + 4]; // rows 4-7
            fma2(acc[0][0], hA.x, w0); fma2(acc[0][1], hA.x, w1);
            fma2(acc[1][0], hA.y, w0); fma2(acc[1][1], hA.y, w1);
            fma2(acc[2][0], hB.x, w0); fma2(acc[2][1], hB.x, w1);
            fma2(acc[3][0], hB.y, w0); fma2(acc[3][1], hB.y, w1);
        }

        float g[8][2];
        #pragma unroll
        for (int p = 0; p < 4; p++) {
            float2 a0 = unpack2(acc[p][0]), a1 = unpack2(acc[p][1]);
            g[2 * p][0]     = sigmoid_f(a0.x);
            g[2 * p + 1][0] = sigmoid_f(a0.y);
            g[2 * p][1]     = sigmoid_f(a1.x);
            g[2 * p + 1][1] = sigmoid_f(a1.y);
        }

        if (tid < 64) {
            // r-gates (cols cg, cg+1 < 128): store rh = r * h_old (transposed).
            #pragma unroll
            for (int c = 0; c < 2; c++) {
                const int col = cg + c;
                float4 h0 = *(const float4*)&h_s[col * SPAD];
                float4 h1 = *(const float4*)&h_s[col * SPAD + 4];
                float4 o0 = make_float4(g[0][c] * h0.x, g[1][c] * h0.y,
                                        g[2][c] * h0.z, g[3][c] * h0.w);
                float4 o1 = make_float4(g[4][c] * h1.x, g[5][c] * h1.y,
                                        g[6][c] * h1.z, g[7][c] * h1.w);
                *(float4*)&rh_s[col * SPAD]     = o0;
                *(float4*)&rh_s[col * SPAD + 4] = o1;
            }
        } else {
            // u-gates (cols >= 128).
            #pragma unroll
            for (int c = 0; c < 2; c++) {
                const int col = cg + c - 128;
                float4 o0 = make_float4(g[0][c], g[1][c], g[2][c], g[3][c]);
                float4 o1 = make_float4(g[4][c], g[5][c], g[6][c], g[7][c]);
                *(float4*)&u_s[col * SPAD]     = o0;
                *(float4*)&u_s[col * SPAD + 4] = o1;
            }
        }
        __syncthreads();

        // ---- Phase C: c = tanh(xc + (r*h) @ Wc_h); h update ----------------
        u64 ac[4];
        ac[0] = pack2(xc[0], xc[1]); ac[1] = pack2(xc[2], xc[3]);
        ac[2] = pack2(xc[4], xc[5]); ac[3] = pack2(xc[6], xc[7]);

        #pragma unroll 4
        for (int k = 0; k < 128; k++) {
            u64 ws = splat2(Wc_s[k * 128 + tid]);
            ulonglong2 pA = *(const ulonglong2*)&rh_s[k * SPAD];
            ulonglong2 pB = *(const ulonglong2*)&rh_s[k * SPAD + 4];
            fma2(ac[0], pA.x, ws); fma2(ac[1], pA.y, ws);
            fma2(ac[2], pB.x, ws); fma2(ac[3], pB.y, ws);
        }

        float cv[8];
        {
            float2 q;
            q = unpack2(ac[0]); cv[0] = tanh_f(q.x); cv[1] = tanh_f(q.y);
            q = unpack2(ac[1]); cv[2] = tanh_f(q.x); cv[3] = tanh_f(q.y);
            q = unpack2(ac[2]); cv[4] = tanh_f(q.x); cv[5] = tanh_f(q.y);
            q = unpack2(ac[3]); cv[6] = tanh_f(q.x); cv[7] = tanh_f(q.y);
        }

        float4 u0 = *(const float4*)&u_s[tid * SPAD];
        float4 u1 = *(const float4*)&u_s[tid * SPAD + 4];
        float4 h0 = *(const float4*)&h_s[tid * SPAD];
        float4 h1 = *(const float4*)&h_s[tid * SPAD + 4];
        float uu[8] = {u0.x, u0.y, u0.z, u0.w, u1.x, u1.y, u1.z, u1.w};
        float hh[8] = {h0.x, h0.y, h0.z, h0.w, h1.x, h1.y, h1.z, h1.w};
        float hn[8];
        #pragma unroll
        for (int i = 0; i < 8; i++) {
            float hw = uu[i] * hh[i] + (1.0f - uu[i]) * cv[i];
            bool v = (t < sl[i]);
            hn[i] = v ? hw : hh[i];
            out[((size_t)(b0 + i) * TT + t) * 128 + tid] = v ? hw : 0.0f;
        }
        *(float4*)&h_s[tid * SPAD]     = make_float4(hn[0], hn[1], hn[2], hn[3]);
        *(float4*)&h_s[tid * SPAD + 4] = make_float4(hn[4], hn[5], hn[6], hn[7]);

        #pragma unroll
        for (int i = 0; i < 8; i++) { xg[i] = xg_n[i]; xc[i] = xc_n[i]; }
        __syncthreads();
    }
}

// ---------------------------------------------------------------------------
extern "C" void kernel_launch(void* const* d_in, const int* in_sizes, int n_in,
                              void* d_out, int out_size)
{
    (void)in_sizes; (void)n_in; (void)out_size;
    const float* X   = (const float*)d_in[0];   // item_his_eb [1024,200,128]
    const int*   sq  = (const int*)  d_in[1];   // seq_len [1024]
    const float* Wg  = (const float*)d_in[2];   // W_gate [256,256]
    const float* bg  = (const float*)d_in[3];   // b_gate [256]
    const float* Wc  = (const float*)d_in[4];   // W_cand [256,128]
    const float* bc  = (const float*)d_in[5];   // b_cand [128]
    float* out = (float*)d_out;                 // [1024,200,128]

    const int smemA = (64 * 132 + 128 * 128) * 4;                       // 99328
    const int smemB = (128 * 256 + 128 * 128 + 3 * 128 * SPAD) * 4;     // 215040
    cudaFuncSetAttribute(precompute_kernel,
                         cudaFuncAttributeMaxDynamicSharedMemorySize, smemA);
    cudaFuncSetAttribute(gru_kernel,
                         cudaFuncAttributeMaxDynamicSharedMemorySize, smemB);

    precompute_kernel<<<3200, 256, smemA>>>(X, Wg, bg, Wc, bc);
    gru_kernel<<<128, 128, smemB>>>(Wg, Wc, sq, out);
}